// round 1
// baseline (speedup 1.0000x reference)
#include <cuda_runtime.h>
#include <cuda_bf16.h>
#include <math.h>

// Problem constants (fixed shapes from reference)
#define BB 4
#define TT 4096
#define DD 1024
#define MM (BB * TT)          // 16384 rows of x
#define TOT (MM * DD)         // 16777216 elements
#define BD (BB * DD)          // 4096

// Scratch: raw GEMM outputs, reused in-place as (a, u) after gate kernel.
__device__ float g_buf0[TOT];  // x@Wr^T  -> a
__device__ float g_buf1[TOT];  // x@Wi^T  -> u
__device__ float g_buf2[TOT];  // x@Wx^T

// ---------------------------------------------------------------------------
// SGEMM: C[m,n] = sum_k A[m,k] * W[n,k]   (both row-major, K contiguous: NT)
// 128x128 block tile, BK=16, 256 threads, 8x8 per-thread micro-tile split as
// two 4-wide float4 groups (tx*4 and 64+tx*4) for conflict-free smem loads.
// ---------------------------------------------------------------------------
#define BM 128
#define BN 128
#define BK 16
#define PAD 4   // keeps 16B row alignment; 2-way conflict only on smem stores

__global__ void __launch_bounds__(256, 2)
sgemm_nt(const float* __restrict__ A, const float* __restrict__ W,
         float* __restrict__ C, int M, int N, int K)
{
    __shared__ float As[BK][BM + PAD];
    __shared__ float Bs[BK][BN + PAD];

    const int tid = threadIdx.x;
    const int tx  = tid & 15;   // n direction (16)
    const int ty  = tid >> 4;   // m direction (16)
    const int bm  = blockIdx.y * BM;
    const int bn  = blockIdx.x * BN;

    const int lr = tid >> 2;         // 0..63 : row within tile
    const int lc = (tid & 3) * 4;    // 0,4,8,12 : k (float4)

    float acc[8][8];
#pragma unroll
    for (int i = 0; i < 8; i++)
#pragma unroll
        for (int j = 0; j < 8; j++) acc[i][j] = 0.f;

    for (int k0 = 0; k0 < K; k0 += BK) {
#pragma unroll
        for (int r = 0; r < 2; r++) {
            const int row = lr + 64 * r;
            float4 va = *(const float4*)(A + (size_t)(bm + row) * K + k0 + lc);
            As[lc + 0][row] = va.x; As[lc + 1][row] = va.y;
            As[lc + 2][row] = va.z; As[lc + 3][row] = va.w;
            float4 vb = *(const float4*)(W + (size_t)(bn + row) * K + k0 + lc);
            Bs[lc + 0][row] = vb.x; Bs[lc + 1][row] = vb.y;
            Bs[lc + 2][row] = vb.z; Bs[lc + 3][row] = vb.w;
        }
        __syncthreads();

#pragma unroll
        for (int k = 0; k < BK; k++) {
            float4 a0 = *(const float4*)&As[k][ty * 4];
            float4 a1 = *(const float4*)&As[k][64 + ty * 4];
            float4 b0 = *(const float4*)&Bs[k][tx * 4];
            float4 b1 = *(const float4*)&Bs[k][64 + tx * 4];
            float af[8] = {a0.x, a0.y, a0.z, a0.w, a1.x, a1.y, a1.z, a1.w};
            float bf[8] = {b0.x, b0.y, b0.z, b0.w, b1.x, b1.y, b1.z, b1.w};
#pragma unroll
            for (int i = 0; i < 8; i++)
#pragma unroll
                for (int j = 0; j < 8; j++)
                    acc[i][j] = fmaf(af[i], bf[j], acc[i][j]);
        }
        __syncthreads();
    }

#pragma unroll
    for (int i = 0; i < 8; i++) {
        const int row = bm + ((i < 4) ? (ty * 4 + i) : (64 + ty * 4 + i - 4));
        float4 o0 = make_float4(acc[i][0], acc[i][1], acc[i][2], acc[i][3]);
        float4 o1 = make_float4(acc[i][4], acc[i][5], acc[i][6], acc[i][7]);
        *(float4*)(C + (size_t)row * N + bn + tx * 4)      = o0;
        *(float4*)(C + (size_t)row * N + bn + 64 + tx * 4) = o1;
    }
}

// ---------------------------------------------------------------------------
// Gate kernel: a = sigmoid(-log8 * sigmoid(rpre + b_r))
//              u = sqrt(max(1 - a*a, 1e-6)) * sigmoid(ipre + b_i) * xw
// In-place: g_buf0 -> a, g_buf1 -> u
// ---------------------------------------------------------------------------
#define LOG8F 2.0794415416798357f

__device__ __forceinline__ float sigmoidf_(float z) {
    return 1.0f / (1.0f + expf(-z));
}

__global__ void __launch_bounds__(256)
gate_kernel(const float* __restrict__ b_r, const float* __restrict__ b_i)
{
    const size_t idx = ((size_t)blockIdx.x * blockDim.x + threadIdx.x) * 4;
    if (idx >= (size_t)TOT) return;

    float4 rp = *(const float4*)&g_buf0[idx];
    float4 ip = *(const float4*)&g_buf1[idx];
    float4 xw = *(const float4*)&g_buf2[idx];
    const int e = (int)(idx & (DD - 1));   // multiple of 4
    float4 brv = *(const float4*)&b_r[e];
    float4 biv = *(const float4*)&b_i[e];

    float a[4], u[4];
    float rr[4] = {rp.x + brv.x, rp.y + brv.y, rp.z + brv.z, rp.w + brv.w};
    float ii[4] = {ip.x + biv.x, ip.y + biv.y, ip.z + biv.z, ip.w + biv.w};
    float xv[4] = {xw.x, xw.y, xw.z, xw.w};
#pragma unroll
    for (int c = 0; c < 4; c++) {
        float r = sigmoidf_(rr[c]);
        // exp(-softplus(log8*r)) == 1/(1+exp(log8*r)) == sigmoid(-log8*r)
        a[c] = sigmoidf_(-LOG8F * r);
        float gate = sqrtf(fmaxf(1.0f - a[c] * a[c], 1e-6f));
        u[c] = gate * sigmoidf_(ii[c]) * xv[c];
    }
    *(float4*)&g_buf0[idx] = make_float4(a[0], a[1], a[2], a[3]);
    *(float4*)&g_buf1[idx] = make_float4(u[0], u[1], u[2], u[3]);
}

// ---------------------------------------------------------------------------
// Scan kernel: h_t = a_t * h_{t-1} + u_t  over T, one thread per (b,d).
// Lanes cover consecutive d -> fully coalesced at every t.
// ---------------------------------------------------------------------------
__global__ void __launch_bounds__(128)
scan_kernel(const float* __restrict__ h0, float* __restrict__ out,
            float* __restrict__ hlast, int write_hlast)
{
    const int bd = blockIdx.x * blockDim.x + threadIdx.x;  // 0..BD-1
    const int b  = bd >> 10;
    const int d  = bd & (DD - 1);

    float h = h0[bd];
    const size_t base = (size_t)b * TT * DD + d;
#pragma unroll 8
    for (int t = 0; t < TT; t++) {
        const size_t idx = base + (size_t)t * DD;
        h = fmaf(g_buf0[idx], h, g_buf1[idx]);
        out[idx] = h;
    }
    if (write_hlast) hlast[bd] = h;
}

// ---------------------------------------------------------------------------
extern "C" void kernel_launch(void* const* d_in, const int* in_sizes, int n_in,
                              void* d_out, int out_size)
{
    const float* x   = (const float*)d_in[0];
    const float* h0  = (const float*)d_in[1];
    const float* W_r = (const float*)d_in[2];
    const float* b_r = (const float*)d_in[3];
    const float* W_i = (const float*)d_in[4];
    const float* b_i = (const float*)d_in[5];
    const float* W_x = (const float*)d_in[6];
    float* out = (float*)d_out;

    float *p0, *p1, *p2;
    cudaGetSymbolAddress((void**)&p0, g_buf0);
    cudaGetSymbolAddress((void**)&p1, g_buf1);
    cudaGetSymbolAddress((void**)&p2, g_buf2);

    dim3 grid(DD / BN, MM / BM);  // (8, 128)
    sgemm_nt<<<grid, 256>>>(x, W_r, p0, MM, DD, DD);
    sgemm_nt<<<grid, 256>>>(x, W_i, p1, MM, DD, DD);
    sgemm_nt<<<grid, 256>>>(x, W_x, p2, MM, DD, DD);

    gate_kernel<<<TOT / (4 * 256), 256>>>(b_r, b_i);

    const int write_h = (out_size >= TOT + BD) ? 1 : 0;
    scan_kernel<<<BD / 128, 128>>>(h0, out, out + (size_t)TOT, write_h);
}

// round 4
// speedup vs baseline: 2.4945x; 2.4945x over previous
#include <cuda_runtime.h>
#include <cstdint>
#include <math.h>

// ---------------------------------------------------------------- constants
#define BB 4
#define TT 4096
#define DD 1024
#define MM (BB * TT)            // 16384
#define TOTL ((size_t)MM * DD)  // 16777216
#define BD (BB * DD)            // 4096
#define CH 16                   // scan chunks per sequence
#define CLEN (TT / CH)          // 256

#define LOG8F 2.0794415416798357f

// ---------------------------------------------------------------- scratch
__device__ float g_a[MM * DD];      // raw zr  -> a
__device__ float g_u[MM * DD];      // raw zi  -> u
__device__ float g_P[BD * CH];
__device__ float g_Q[BD * CH];
__device__ float g_S[BD * CH];

// ---------------------------------------------------------------- tf32 utils
__device__ __forceinline__ float tf32r(float x) {
    uint32_t o;
    asm("cvt.rna.tf32.f32 %0, %1;" : "=r"(o) : "f"(x));
    return __uint_as_float(o);
}
__device__ __forceinline__ float4 cvt4(float4 v) {
    v.x = tf32r(v.x); v.y = tf32r(v.y); v.z = tf32r(v.z); v.w = tf32r(v.w);
    return v;
}

__device__ __forceinline__ void mma_tf32(float* d, const uint32_t* a, const uint32_t* b) {
    asm volatile(
        "mma.sync.aligned.m16n8k8.row.col.f32.tf32.tf32.f32 "
        "{%0,%1,%2,%3}, {%4,%5,%6,%7}, {%8,%9}, {%0,%1,%2,%3};"
        : "+f"(d[0]), "+f"(d[1]), "+f"(d[2]), "+f"(d[3])
        : "r"(a[0]), "r"(a[1]), "r"(a[2]), "r"(a[3]), "r"(b[0]), "r"(b[1]));
}

// ---------------------------------------------------------------- GEMM
// C[m,n] = sum_k A[m,k] * W[n,k]  (NT). 128x128x32 CTA tile, 8 warps (2Mx4N),
// 64x32 warp tile of m16n8k8 mmas, double-buffered smem, padded [row][k].
#define BM 128
#define BN 128
#define BK 32
#define NK (DD / BK)            // 32
#define RS 36                   // padded row stride (floats) -> conflict-free frags
#define SMEM_BYTES (2 * 2 * 128 * RS * 4)   // 73728

#define SA(s, m, k) As[((s) * 128 + (m)) * RS + (k)]
#define SB(s, n, k) Bs[((s) * 128 + (n)) * RS + (k)]

template <int GATE>
__global__ void __launch_bounds__(256, 2)
gemm_tf32(const float* __restrict__ A, const float* __restrict__ W,
          float* __restrict__ C,
          const float* __restrict__ br, const float* __restrict__ bi)
{
    extern __shared__ float smem[];
    float* As = smem;
    float* Bs = smem + 2 * 128 * RS;

    const int tid = threadIdx.x;
    const int wid = tid >> 5;
    const int lane = tid & 31;
    const int r = lane >> 2;      // group 0..7
    const int c = lane & 3;       // tid-in-group
    const int mw = (wid >> 2) * 64;   // warp m offset
    const int nw = (wid & 3) * 32;    // warp n offset
    const int bm = blockIdx.y * BM;
    const int bn = blockIdx.x * BN;

    const int lrow = tid >> 1;            // 0..127
    const int lc4  = (tid & 1) * 4;       // 0 or 4 (float4 col)

    float acc[4][4][4];
#pragma unroll
    for (int i = 0; i < 4; i++)
#pragma unroll
        for (int j = 0; j < 4; j++)
#pragma unroll
            for (int q = 0; q < 4; q++) acc[i][j][q] = 0.f;

    // prologue: stage 0
#pragma unroll
    for (int i = 0; i < 2; i++) {
        const int col4 = lc4 + i;   // wait: need cols 0..7; do below properly
    }
    // load helper (each thread: 4 float4 for A, 4 for B per tile)
    // mapping: u = tid + 256*i, row = u>>3 (0..127), col4 = u&7 (0..7)
#pragma unroll
    for (int i = 0; i < 4; i++) {
        const int u = tid + 256 * i;
        const int row = u >> 3, col4 = u & 7;
        float4 va = cvt4(*(const float4*)(A + (size_t)(bm + row) * DD + col4 * 4));
        *(float4*)&SA(0, row, col4 * 4) = va;
        float4 vb = cvt4(*(const float4*)(W + (size_t)(bn + row) * DD + col4 * 4));
        *(float4*)&SB(0, row, col4 * 4) = vb;
    }
    __syncthreads();

    for (int kt = 0; kt < NK; kt++) {
        const int s = kt & 1;
        if (kt + 1 < NK) {
            const int k0 = (kt + 1) * BK;
#pragma unroll
            for (int i = 0; i < 4; i++) {
                const int u = tid + 256 * i;
                const int row = u >> 3, col4 = u & 7;
                float4 va = cvt4(*(const float4*)(A + (size_t)(bm + row) * DD + k0 + col4 * 4));
                *(float4*)&SA(s ^ 1, row, col4 * 4) = va;
                float4 vb = cvt4(*(const float4*)(W + (size_t)(bn + row) * DD + k0 + col4 * 4));
                *(float4*)&SB(s ^ 1, row, col4 * 4) = vb;
            }
        }
#pragma unroll
        for (int kk = 0; kk < BK; kk += 8) {
            uint32_t af[4][4], bf[4][2];
#pragma unroll
            for (int mi = 0; mi < 4; mi++) {
                const float* pa = &SA(s, mw + mi * 16 + r, kk + c);
                af[mi][0] = __float_as_uint(pa[0]);
                af[mi][1] = __float_as_uint(pa[8 * RS]);
                af[mi][2] = __float_as_uint(pa[4]);
                af[mi][3] = __float_as_uint(pa[8 * RS + 4]);
            }
#pragma unroll
            for (int ni = 0; ni < 4; ni++) {
                const float* pb = &SB(s, nw + ni * 8 + r, kk + c);
                bf[ni][0] = __float_as_uint(pb[0]);
                bf[ni][1] = __float_as_uint(pb[4]);
            }
#pragma unroll
            for (int mi = 0; mi < 4; mi++)
#pragma unroll
                for (int ni = 0; ni < 4; ni++)
                    mma_tf32(acc[mi][ni], af[mi], bf[ni]);
        }
        __syncthreads();
    }

    // ---- epilogue
#pragma unroll
    for (int mi = 0; mi < 4; mi++) {
#pragma unroll
        for (int ni = 0; ni < 4; ni++) {
            const int m0 = bm + mw + mi * 16 + r;
            const int n  = bn + nw + ni * 8 + c * 2;
            if (GATE == 0) {
                *(float2*)(C + (size_t)m0 * DD + n) =
                    make_float2(acc[mi][ni][0], acc[mi][ni][1]);
                *(float2*)(C + (size_t)(m0 + 8) * DD + n) =
                    make_float2(acc[mi][ni][2], acc[mi][ni][3]);
            } else {
                const float br0 = __ldg(br + n), br1 = __ldg(br + n + 1);
                const float bi0 = __ldg(bi + n), bi1 = __ldg(bi + n + 1);
#pragma unroll
                for (int h = 0; h < 2; h++) {
                    const size_t idx = (size_t)(m0 + 8 * h) * DD + n;
                    float2 zr = *(float2*)&g_a[idx];
                    float2 zi = *(float2*)&g_u[idx];
                    float av[2], uv[2];
#pragma unroll
                    for (int q = 0; q < 2; q++) {
                        const float zrv = (q ? zr.y : zr.x) + (q ? br1 : br0);
                        const float ziv = (q ? zi.y : zi.x) + (q ? bi1 : bi0);
                        const float rr = 1.f / (1.f + __expf(-zrv));
                        // exp(-softplus(log8*r)) == sigmoid(-log8*r)
                        const float a = 1.f / (1.f + __expf(LOG8F * rr));
                        const float g = sqrtf(fmaxf(1.f - a * a, 1e-6f));
                        const float iv = 1.f / (1.f + __expf(-ziv));
                        av[q] = a;
                        uv[q] = g * iv * acc[mi][ni][h * 2 + q];
                    }
                    *(float2*)&g_a[idx] = make_float2(av[0], av[1]);
                    *(float2*)&g_u[idx] = make_float2(uv[0], uv[1]);
                }
            }
        }
    }
}

// ---------------------------------------------------------------- scan (3-pass)
__global__ void __launch_bounds__(256) scan_pass1() {
    const int g = blockIdx.x * 256 + threadIdx.x;        // 0..65535
    const int d = g & (DD - 1);
    const int ch = (g >> 10) & (CH - 1);
    const int b = g >> 14;
    const size_t base = (size_t)b * TT * DD + (size_t)ch * CLEN * DD + d;
    float P = 1.f, Q = 0.f;
#pragma unroll 8
    for (int j = 0; j < CLEN; j++) {
        const float a = g_a[base + (size_t)j * DD];
        const float u = g_u[base + (size_t)j * DD];
        P *= a;
        Q = fmaf(a, Q, u);
    }
    g_P[g] = P;
    g_Q[g] = Q;
}

__global__ void __launch_bounds__(256) scan_pass2(const float* __restrict__ h0,
                                                  float* __restrict__ hlast) {
    const int bd = blockIdx.x * 256 + threadIdx.x;       // 0..4095
    const int b = bd >> 10, d = bd & (DD - 1);
    float S = h0[bd];
#pragma unroll
    for (int ch = 0; ch < CH; ch++) {
        const int idx = ((b * CH + ch) << 10) | d;
        g_S[idx] = S;
        S = fmaf(g_P[idx], S, g_Q[idx]);
    }
    hlast[bd] = S;
}

__global__ void __launch_bounds__(256) scan_pass3(float* __restrict__ out) {
    const int g = blockIdx.x * 256 + threadIdx.x;        // 0..65535
    const int d = g & (DD - 1);
    const int ch = (g >> 10) & (CH - 1);
    const int b = g >> 14;
    const size_t base = (size_t)b * TT * DD + (size_t)ch * CLEN * DD + d;
    float h = g_S[g];
#pragma unroll 8
    for (int j = 0; j < CLEN; j++) {
        h = fmaf(g_a[base + (size_t)j * DD], h, g_u[base + (size_t)j * DD]);
        out[base + (size_t)j * DD] = h;
    }
}

// ---------------------------------------------------------------- launch
extern "C" void kernel_launch(void* const* d_in, const int* in_sizes, int n_in,
                              void* d_out, int out_size)
{
    const float* x   = (const float*)d_in[0];
    const float* h0  = (const float*)d_in[1];
    const float* W_r = (const float*)d_in[2];
    const float* b_r = (const float*)d_in[3];
    const float* W_i = (const float*)d_in[4];
    const float* b_i = (const float*)d_in[5];
    const float* W_x = (const float*)d_in[6];
    float* out = (float*)d_out;

    float *pa, *pu;
    cudaGetSymbolAddress((void**)&pa, g_a);
    cudaGetSymbolAddress((void**)&pu, g_u);

    cudaFuncSetAttribute(gemm_tf32<0>, cudaFuncAttributeMaxDynamicSharedMemorySize, SMEM_BYTES);
    cudaFuncSetAttribute(gemm_tf32<1>, cudaFuncAttributeMaxDynamicSharedMemorySize, SMEM_BYTES);

    dim3 grid(DD / BN, MM / BM);   // (8, 128)
    gemm_tf32<0><<<grid, 256, SMEM_BYTES>>>(x, W_r, pa, nullptr, nullptr);
    gemm_tf32<0><<<grid, 256, SMEM_BYTES>>>(x, W_i, pu, nullptr, nullptr);
    gemm_tf32<1><<<grid, 256, SMEM_BYTES>>>(x, W_x, nullptr, b_r, b_i);

    scan_pass1<<<(BD * CH) / 256, 256>>>();
    scan_pass2<<<BD / 256, 256>>>(h0, out + TOTL);
    scan_pass3<<<(BD * CH) / 256, 256>>>(out);
}